// round 12
// baseline (speedup 1.0000x reference)
#include <cuda_runtime.h>
#include <cuda_bf16.h>

// HeadWise_JSD: out = (0.5/12) * sum p * (log p - log q)   [kl_pm == 0 exactly]
// Streaming reduction over 2 x 201 MB fp32.
// Config map: codegen quality tracks reg count (32 regs = squeezed schedule
// -> 6.2-6.4 TB/s; 36 regs -> 6.74 TB/s). R12 = R9's exact binary
// (launch_bounds(256,6), regs=36) but grid 1036: 36*1792=64512<=65536 so the
// runtime fits 7 blocks/SM -> good codegen x 56 warps/SM.

static __device__ __forceinline__ float term(float p, float q) {
    // p * lg2(p/q): MUFU.RCP + FMUL + MUFU.LG2 + FMUL. abs err ~2^-22/op,
    // weighted by sum(p) vs output O(250) -> ~1e-5 worst case. Fine vs 1e-3.
    float r = __fdividef(p, q);
    return p * __log2f(r);
}

static __device__ __forceinline__ float term4(float4 pv, float4 qv) {
    float a = term(pv.x, qv.x) + term(pv.y, qv.y);
    float b = term(pv.z, qv.z) + term(pv.w, qv.w);
    return a + b;
}

__global__ void jsd_zero_kernel(float* out) {
    if (threadIdx.x == 0 && blockIdx.x == 0) out[0] = 0.0f;
}

__global__ __launch_bounds__(256, 6) void jsd_reduce_kernel(
    const float4* __restrict__ p4,
    const float4* __restrict__ q4,
    float* __restrict__ out,
    int n4)
{
    const int stride = gridDim.x * 256;
    int i = blockIdx.x * 256 + threadIdx.x;

    float a0 = 0.0f, a1 = 0.0f;

    // 4 front-batched streaming LDG.128.CS per macro-iter
    for (; i + stride < n4; i += 2 * stride) {
        float4 p0 = __ldcs(p4 + i);
        float4 p1 = __ldcs(p4 + i + stride);
        float4 q0 = __ldcs(q4 + i);
        float4 q1 = __ldcs(q4 + i + stride);
        a0 += term4(p0, q0);
        a1 += term4(p1, q1);
    }
    for (; i < n4; i += stride)
        a0 += term4(__ldcs(p4 + i), __ldcs(q4 + i));

    // log2-units -> nats
    float acc = (a0 + a1) * 0.69314718055994531f;

    #pragma unroll
    for (int o = 16; o; o >>= 1)
        acc += __shfl_xor_sync(0xffffffffu, acc, o);

    __shared__ float smem[8];
    int lane = threadIdx.x & 31;
    int warp = threadIdx.x >> 5;
    if (lane == 0) smem[warp] = acc;
    __syncthreads();

    if (warp == 0) {
        float v = (lane < 8) ? smem[lane] : 0.0f;
        #pragma unroll
        for (int o = 4; o; o >>= 1)
            v += __shfl_xor_sync(0xffffffffu, v, o);
        if (lane == 0)
            atomicAdd(out, v * (0.5f / 12.0f));
    }
}

extern "C" void kernel_launch(void* const* d_in, const int* in_sizes, int n_in,
                              void* d_out, int out_size) {
    const float4* p4 = (const float4*)d_in[0];
    const float4* q4 = (const float4*)d_in[1];
    float* out = (float*)d_out;

    int n  = in_sizes[0];     // 1024*12*4096
    int n4 = n >> 2;          // 12,582,912 float4 pairs

    jsd_zero_kernel<<<1, 32>>>(out);

    // 1036 blocks: with regs=36 the runtime fits 7 blocks/SM (one full wave
    // at 56 warps/SM) using the proven 36-reg codegen.
    jsd_reduce_kernel<<<1036, 256>>>(p4, q4, out, n4);
}

// round 13
// speedup vs baseline: 1.0501x; 1.0501x over previous
#include <cuda_runtime.h>
#include <cuda_bf16.h>
#include <cstdint>

// HeadWise_JSD: out = (0.5/12) * sum p * (log p - log q)   [kl_pm == 0 exactly]
// Streaming reduction over 2 x 201 MB fp32.
// LDG config space exhausted: 48 warps/SM x 36-reg schedule = 6.74 TB/s peak
// (61.9us). R13: cp.async.bulk (TMA) pipeline -- MLP from stages-in-flight
// (6 blocks x 4 stages x 8KB = 192KB/SM), not registers. Warps only do
// SMEM->MUFU math. Grid-stride chunk interleave (proven best DRAM pattern).

#define NS        4        // pipeline stages (power of 2)
#define STAGE_F4  256      // float4 per array per stage = 4 KB
#define STAGE_BYTES 4096
#define THREADS   256

static __device__ __forceinline__ float term(float p, float q) {
    // p * lg2(p/q): MUFU.RCP + FMUL + MUFU.LG2 + FMUL; ~1e-5 worst-case rel.
    float r = __fdividef(p, q);
    return p * __log2f(r);
}
static __device__ __forceinline__ float term4(float4 pv, float4 qv) {
    float a = term(pv.x, qv.x) + term(pv.y, qv.y);
    float b = term(pv.z, qv.z) + term(pv.w, qv.w);
    return a + b;
}

__global__ void jsd_zero_kernel(float* out) {
    if (threadIdx.x == 0 && blockIdx.x == 0) out[0] = 0.0f;
}

__global__ __launch_bounds__(256, 6) void jsd_tma_kernel(
    const float4* __restrict__ p4,
    const float4* __restrict__ q4,
    float* __restrict__ out,
    int nchunks)               // n4 / STAGE_F4
{
    __shared__ __align__(16) float4 sp[NS][STAGE_F4];   // 16 KB
    __shared__ __align__(16) float4 sq[NS][STAGE_F4];   // 16 KB
    __shared__ __align__(8)  unsigned long long mbar[NS];
    __shared__ float red[8];

    const int tid = threadIdx.x;
    const int G   = gridDim.x;

    unsigned mb[NS];
    #pragma unroll
    for (int s = 0; s < NS; s++)
        mb[s] = (unsigned)__cvta_generic_to_shared(&mbar[s]);

    if (tid == 0) {
        #pragma unroll
        for (int s = 0; s < NS; s++)
            asm volatile("mbarrier.init.shared.b64 [%0], 1;"
                         :: "r"(mb[s]) : "memory");
        asm volatile("fence.proxy.async.shared::cta;" ::: "memory");
    }
    __syncthreads();

    // prologue: fill all NS stages
    if (tid == 0) {
        #pragma unroll
        for (int k = 0; k < NS; k++) {
            int c = blockIdx.x + k * G;
            if (c < nchunks) {
                asm volatile("mbarrier.arrive.expect_tx.shared.b64 _, [%0], %1;"
                             :: "r"(mb[k]), "r"(2 * STAGE_BYTES) : "memory");
                unsigned dp = (unsigned)__cvta_generic_to_shared(&sp[k][0]);
                unsigned dq = (unsigned)__cvta_generic_to_shared(&sq[k][0]);
                asm volatile(
                    "cp.async.bulk.shared::cta.global.mbarrier::complete_tx::bytes [%0], [%1], %2, [%3];"
                    :: "r"(dp), "l"(p4 + (size_t)c * STAGE_F4),
                       "r"(STAGE_BYTES), "r"(mb[k]) : "memory");
                asm volatile(
                    "cp.async.bulk.shared::cta.global.mbarrier::complete_tx::bytes [%0], [%1], %2, [%3];"
                    :: "r"(dq), "l"(q4 + (size_t)c * STAGE_F4),
                       "r"(STAGE_BYTES), "r"(mb[k]) : "memory");
            }
        }
    }

    float acc = 0.0f;
    int t = 0;
    for (int c = blockIdx.x; c < nchunks; c += G, t++) {
        int s  = t & (NS - 1);
        int ph = (t >> 2) & 1;       // NS == 4

        // wait full (acquire; HW-sleep try_wait loop)
        unsigned done = 0;
        while (!done)
            asm volatile(
                "{\n\t.reg .pred p;\n\t"
                "mbarrier.try_wait.parity.acquire.cta.shared::cta.b64 p, [%1], %2, 0x989680;\n\t"
                "selp.b32 %0, 1, 0, p;\n\t}"
                : "=r"(done) : "r"(mb[s]), "r"(ph) : "memory");

        float4 pv = sp[s][tid];
        float4 qv = sq[s][tid];
        acc += term4(pv, qv);

        __syncthreads();             // slot s fully consumed by all threads

        if (tid == 0) {
            int cn = c + NS * G;
            if (cn < nchunks) {
                asm volatile("fence.proxy.async.shared::cta;" ::: "memory");
                asm volatile("mbarrier.arrive.expect_tx.shared.b64 _, [%0], %1;"
                             :: "r"(mb[s]), "r"(2 * STAGE_BYTES) : "memory");
                unsigned dp = (unsigned)__cvta_generic_to_shared(&sp[s][0]);
                unsigned dq = (unsigned)__cvta_generic_to_shared(&sq[s][0]);
                asm volatile(
                    "cp.async.bulk.shared::cta.global.mbarrier::complete_tx::bytes [%0], [%1], %2, [%3];"
                    :: "r"(dp), "l"(p4 + (size_t)cn * STAGE_F4),
                       "r"(STAGE_BYTES), "r"(mb[s]) : "memory");
                asm volatile(
                    "cp.async.bulk.shared::cta.global.mbarrier::complete_tx::bytes [%0], [%1], %2, [%3];"
                    :: "r"(dq), "l"(q4 + (size_t)cn * STAGE_F4),
                       "r"(STAGE_BYTES), "r"(mb[s]) : "memory");
            }
        }
    }

    // log2-units -> nats
    acc *= 0.69314718055994531f;

    #pragma unroll
    for (int o = 16; o; o >>= 1)
        acc += __shfl_xor_sync(0xffffffffu, acc, o);

    int lane = tid & 31;
    int warp = tid >> 5;
    if (lane == 0) red[warp] = acc;
    __syncthreads();

    if (warp == 0) {
        float v = (lane < 8) ? red[lane] : 0.0f;
        #pragma unroll
        for (int o = 4; o; o >>= 1)
            v += __shfl_xor_sync(0xffffffffu, v, o);
        if (lane == 0)
            atomicAdd(out, v * (0.5f / 12.0f));
    }
}

extern "C" void kernel_launch(void* const* d_in, const int* in_sizes, int n_in,
                              void* d_out, int out_size) {
    const float4* p4 = (const float4*)d_in[0];
    const float4* q4 = (const float4*)d_in[1];
    float* out = (float*)d_out;

    int n       = in_sizes[0];            // 50,331,648 per array
    int n4      = n >> 2;                 // 12,582,912 float4
    int nchunks = n4 / STAGE_F4;          // 49,152 chunks of 1024 floats

    jsd_zero_kernel<<<1, 32>>>(out);

    // 148 SMs x 6 blocks = 888: one full wave (SMEM ~32.1KB/block -> 6/SM)
    jsd_tma_kernel<<<888, THREADS>>>(p4, q4, out, nchunks);
}

// round 14
// speedup vs baseline: 1.1273x; 1.0735x over previous
#include <cuda_runtime.h>
#include <cuda_bf16.h>

// HeadWise_JSD: out = (0.5/12) * sum p * (log p - log q)   [kl_pm == 0 exactly]
// Streaming reduction over 2 x 201 MB fp32.
// Config map so far (TB/s): LDG 32w=6.20, 48w/36reg=6.74 (best, 61.9us),
// 56w=infeasible (reg granule), 64w/32reg=6.20, TMA pipeline=6.15.
// R14: last untested cell -- 48 warps x 6-deep batch (288 lines/SM in
// flight; 42-reg budget via launch_bounds(256,6), no 32-reg squeeze).

static __device__ __forceinline__ float term(float p, float q) {
    // p * lg2(p/q): MUFU.RCP + FMUL + MUFU.LG2 + FMUL; ~1e-5 worst-case rel.
    float r = __fdividef(p, q);
    return p * __log2f(r);
}

static __device__ __forceinline__ float term4(float4 pv, float4 qv) {
    float a = term(pv.x, qv.x) + term(pv.y, qv.y);
    float b = term(pv.z, qv.z) + term(pv.w, qv.w);
    return a + b;
}

__global__ void jsd_zero_kernel(float* out) {
    if (threadIdx.x == 0 && blockIdx.x == 0) out[0] = 0.0f;
}

__global__ __launch_bounds__(256, 6) void jsd_reduce_kernel(
    const float4* __restrict__ p4,
    const float4* __restrict__ q4,
    float* __restrict__ out,
    int n4)
{
    const int stride = gridDim.x * 256;
    int i = blockIdx.x * 256 + threadIdx.x;

    float a0 = 0.0f, a1 = 0.0f, a2 = 0.0f;

    // 6 front-batched streaming LDG.128.CS per macro-iter at 48 warps/SM
    for (; i + 2 * stride < n4; i += 3 * stride) {
        float4 p0 = __ldcs(p4 + i);
        float4 p1 = __ldcs(p4 + i + stride);
        float4 p2 = __ldcs(p4 + i + 2 * stride);
        float4 q0 = __ldcs(q4 + i);
        float4 q1 = __ldcs(q4 + i + stride);
        float4 q2 = __ldcs(q4 + i + 2 * stride);
        a0 += term4(p0, q0);
        a1 += term4(p1, q1);
        a2 += term4(p2, q2);
    }
    for (; i < n4; i += stride)
        a0 += term4(__ldcs(p4 + i), __ldcs(q4 + i));

    // log2-units -> nats
    float acc = (a0 + a1 + a2) * 0.69314718055994531f;

    #pragma unroll
    for (int o = 16; o; o >>= 1)
        acc += __shfl_xor_sync(0xffffffffu, acc, o);

    __shared__ float smem[8];
    int lane = threadIdx.x & 31;
    int warp = threadIdx.x >> 5;
    if (lane == 0) smem[warp] = acc;
    __syncthreads();

    if (warp == 0) {
        float v = (lane < 8) ? smem[lane] : 0.0f;
        #pragma unroll
        for (int o = 4; o; o >>= 1)
            v += __shfl_xor_sync(0xffffffffu, v, o);
        if (lane == 0)
            atomicAdd(out, v * (0.5f / 12.0f));
    }
}

extern "C" void kernel_launch(void* const* d_in, const int* in_sizes, int n_in,
                              void* d_out, int out_size) {
    const float4* p4 = (const float4*)d_in[0];
    const float4* q4 = (const float4*)d_in[1];
    float* out = (float*)d_out;

    int n  = in_sizes[0];     // 1024*12*4096
    int n4 = n >> 2;          // 12,582,912 float4 pairs

    jsd_zero_kernel<<<1, 32>>>(out);

    // 148 SMs x 6 blocks = 888 blocks: one full wave at 48 warps/SM
    jsd_reduce_kernel<<<888, 256>>>(p4, q4, out, n4);
}

// round 15
// speedup vs baseline: 1.1664x; 1.0347x over previous
#include <cuda_runtime.h>
#include <cuda_bf16.h>

// HeadWise_JSD: out = (0.5/12) * sum p * (log p - log q)   [kl_pm == 0 exactly,
// since m = log(0.5*(p+p)) == log(p) bit-exactly].
// Streaming reduction over 2 x 201 MB fp32.
//
// FINAL (R9 config, re-frozen after full config-space sweep):
//   48 warps/SM (6 blocks x 256, one full wave of 888 blocks), 4-deep
//   front-batched LDG.128.CS, 36-reg schedule, light math
//   (2 MUFU + 2 FMUL per element via p * lg2(p/q)).
// Measured 6.74 TB/s (84% of spec) -- every tested deviation (32/56/64 warps,
// 6/8-deep batches, 32/40-reg codegen, TMA pipeline, contiguous chunks,
// fused finalize) lost 6-15%. This is the machine limit for this pattern.

static __device__ __forceinline__ float term(float p, float q) {
    // p * lg2(p/q): MUFU.RCP + FMUL + MUFU.LG2 + FMUL. abs err ~2^-22/op,
    // weighted by sum(p)=12288 vs output O(250) -> ~1e-5 worst case rel.
    float r = __fdividef(p, q);
    return p * __log2f(r);
}

static __device__ __forceinline__ float term4(float4 pv, float4 qv) {
    float a = term(pv.x, qv.x) + term(pv.y, qv.y);
    float b = term(pv.z, qv.z) + term(pv.w, qv.w);
    return a + b;
}

__global__ void jsd_zero_kernel(float* out) {
    if (threadIdx.x == 0 && blockIdx.x == 0) out[0] = 0.0f;
}

__global__ __launch_bounds__(256, 6) void jsd_reduce_kernel(
    const float4* __restrict__ p4,
    const float4* __restrict__ q4,
    float* __restrict__ out,
    int n4)
{
    const int stride = gridDim.x * 256;
    int i = blockIdx.x * 256 + threadIdx.x;

    float a0 = 0.0f, a1 = 0.0f;

    // 4 front-batched streaming LDG.128.CS per macro-iter; chip-level MLP
    // from 48 warps/SM x 4 lines each (the measured sweet spot).
    for (; i + stride < n4; i += 2 * stride) {
        float4 p0 = __ldcs(p4 + i);
        float4 p1 = __ldcs(p4 + i + stride);
        float4 q0 = __ldcs(q4 + i);
        float4 q1 = __ldcs(q4 + i + stride);
        a0 += term4(p0, q0);
        a1 += term4(p1, q1);
    }
    for (; i < n4; i += stride)
        a0 += term4(__ldcs(p4 + i), __ldcs(q4 + i));

    // log2-units -> nats
    float acc = (a0 + a1) * 0.69314718055994531f;

    #pragma unroll
    for (int o = 16; o; o >>= 1)
        acc += __shfl_xor_sync(0xffffffffu, acc, o);

    __shared__ float smem[8];
    int lane = threadIdx.x & 31;
    int warp = threadIdx.x >> 5;
    if (lane == 0) smem[warp] = acc;
    __syncthreads();

    if (warp == 0) {
        float v = (lane < 8) ? smem[lane] : 0.0f;
        #pragma unroll
        for (int o = 4; o; o >>= 1)
            v += __shfl_xor_sync(0xffffffffu, v, o);
        if (lane == 0)
            atomicAdd(out, v * (0.5f / 12.0f));
    }
}

extern "C" void kernel_launch(void* const* d_in, const int* in_sizes, int n_in,
                              void* d_out, int out_size) {
    const float4* p4 = (const float4*)d_in[0];
    const float4* q4 = (const float4*)d_in[1];
    float* out = (float*)d_out;

    int n  = in_sizes[0];     // 1024*12*4096
    int n4 = n >> 2;          // 12,582,912 float4 pairs

    jsd_zero_kernel<<<1, 32>>>(out);

    // 148 SMs x 6 blocks = 888 blocks: one full wave at 48 warps/SM
    jsd_reduce_kernel<<<888, 256>>>(p4, q4, out, n4);
}